// round 9
// baseline (speedup 1.0000x reference)
#include <cuda_runtime.h>
#include <cstdint>

#define CHN 128
#define HH  128
#define WW  128
#define TH  4
#define CSPLIT 4
#define CPB (CHN/CSPLIT)   // 32 channels per block

typedef unsigned long long ull;

__constant__ float c_w[CHN * 25];
__constant__ float c_b[CHN];

__device__ __forceinline__ ull pack2(float lo, float hi) {
    ull r; asm("mov.b64 %0, {%1, %2};" : "=l"(r) : "f"(lo), "f"(hi)); return r;
}
__device__ __forceinline__ void unpack2(ull v, float& lo, float& hi) {
    asm("mov.b64 {%0, %1}, %2;" : "=f"(lo), "=f"(hi) : "l"(v));
}
__device__ __forceinline__ ull mul2(ull a, ull b) {
    ull d; asm("mul.rn.f32x2 %0, %1, %2;" : "=l"(d) : "l"(a), "l"(b)); return d;
}
__device__ __forceinline__ ull fma2(ull a, ull b, ull c) {
    ull d; asm("fma.rn.f32x2 %0, %1, %2, %3;" : "=l"(d) : "l"(a), "l"(b), "l"(c)); return d;
}
__device__ __forceinline__ ull add2(ull a, ull b) {
    ull d; asm("add.rn.f32x2 %0, %1, %2;" : "=l"(d) : "l"(a), "l"(b)); return d;
}
__device__ __forceinline__ ull dup2(float v) {
    ull r; asm("mov.b64 %0, {%1, %1};" : "=l"(r) : "f"(v)); return r;
}

__global__ __launch_bounds__(256, 3)
void dwconv_ksa_kernel(const float* __restrict__ x,
                       const float* __restrict__ ksa,
                       float* __restrict__ out)
{
    // grid: (H/TH, N, CSPLIT)=(32,4,4)=512 blocks; block: (64, TH)
    const int tx = threadIdx.x;            // 0..63 -> w-pair
    const int ty = threadIdx.y;            // 0..3
    const int h0 = blockIdx.x * TH;
    const int n  = blockIdx.y;
    const int c0 = blockIdx.z * CPB;

    const int h  = h0 + ty;
    const int w0 = tx * 2;

    // ---- ksa for this pixel pair -> packed registers, boundary masks folded ----
    ull kk2[25];
    const float* ksabase = ksa + ((size_t)(n * 25) * HH + h) * WW + w0;
    #pragma unroll
    for (int t = 0; t < 25; t++) {
        float2 v = *(const float2*)(ksabase + (size_t)t * HH * WW);
        const int i = t / 5, j = t % 5;
        const int r = h + i - 2;
        const bool rok = (r >= 0) && (r < HH);
        const int cA = w0 + j - 2;
        const int cB = cA + 1;
        v.x = (rok && cA >= 0 && cA < WW) ? v.x : 0.0f;
        v.y = (rok && cB >= 0 && cB < WW) ? v.y : 0.0f;
        kk2[t] = pack2(v.x, v.y);
    }

    // clamped row offsets (garbage rows masked by kk==0)
    int rowoff[5];
    #pragma unroll
    for (int i = 0; i < 5; i++) {
        int r = h + i - 2;
        r = r < 0 ? 0 : (r > HH - 1 ? HH - 1 : r);
        rowoff[i] = r * WW;
    }
    const int e0 = (w0 - 2 < 0) ? 0 : (w0 - 2);
    const int e2 = (w0 + 2 > WW - 2) ? (WW - 2) : (w0 + 2);

    const float* xn   = x   + (size_t)(n * CHN + c0) * HH * WW;
    float*       outp = out + ((size_t)(n * CHN + c0) * HH + h) * WW + w0;

    // one channel per iteration; weights/bias from constant cache (no L1tex)
    #pragma unroll 1
    for (int cl = 0; cl < CPB; ++cl) {
        const float* xc = xn + (size_t)cl * HH * WW;
        const float* wc = c_w + (c0 + cl) * 25;

        ull accA = dup2(c_b[c0 + cl]);     // acc init = {bias,bias}
        ull accB = 0ULL;

        #pragma unroll
        for (int i = 0; i < 5; i++) {
            const float* row = xc + rowoff[i];
            const float2 A = *(const float2*)(row + e0);
            const float2 B = *(const float2*)(row + w0);
            const float2 C = *(const float2*)(row + e2);

            const ull q0 = pack2(A.x, A.y);
            const ull q1 = pack2(A.y, B.x);
            const ull q2 = pack2(B.x, B.y);
            const ull q3 = pack2(B.y, C.x);
            const ull q4 = pack2(C.x, C.y);

            accA = fma2(mul2(kk2[i*5+0], dup2(wc[i*5+0])), q0, accA);
            accB = fma2(mul2(kk2[i*5+1], dup2(wc[i*5+1])), q1, accB);
            accA = fma2(mul2(kk2[i*5+2], dup2(wc[i*5+2])), q2, accA);
            accB = fma2(mul2(kk2[i*5+3], dup2(wc[i*5+3])), q3, accB);
            accA = fma2(mul2(kk2[i*5+4], dup2(wc[i*5+4])), q4, accA);
        }

        ull r2 = add2(accA, accB);
        float a0, a1;
        unpack2(r2, a0, a1);
        *(float2*)(outp + (size_t)cl * HH * WW) = make_float2(a0, a1);
    }
}

extern "C" void kernel_launch(void* const* d_in, const int* in_sizes, int n_in,
                              void* d_out, int out_size)
{
    const float* x   = (const float*)d_in[0];
    const float* ksa = (const float*)d_in[1];
    const float* w   = (const float*)d_in[2];
    const float* b   = (const float*)d_in[3];
    float* out = (float*)d_out;

    const int n_batch = in_sizes[0] / (CHN * HH * WW);   // 4

    cudaMemcpyToSymbolAsync(c_w, w, CHN * 25 * sizeof(float), 0, cudaMemcpyDeviceToDevice);
    cudaMemcpyToSymbolAsync(c_b, b, CHN * sizeof(float), 0, cudaMemcpyDeviceToDevice);

    dim3 block(64, TH);
    dim3 grid(HH / TH, n_batch, CSPLIT);
    dwconv_ksa_kernel<<<grid, block>>>(x, ksa, out);
}

// round 11
// speedup vs baseline: 1.1758x; 1.1758x over previous
#include <cuda_runtime.h>
#include <cstdint>

#define CHN 128
#define HH  128
#define WW  128
#define TH  4
#define CSPLIT 4
#define CPB (CHN/CSPLIT)   // 32 channels per block

typedef unsigned long long ull;

__constant__ float c_w[CHN * 25];
__constant__ float c_b[CHN];

__device__ __forceinline__ ull pack2(float lo, float hi) {
    ull r; asm("mov.b64 %0, {%1, %2};" : "=l"(r) : "f"(lo), "f"(hi)); return r;
}
__device__ __forceinline__ void unpack2(ull v, float& lo, float& hi) {
    asm("mov.b64 {%0, %1}, %2;" : "=f"(lo), "=f"(hi) : "l"(v));
}
__device__ __forceinline__ ull mul2(ull a, ull b) {
    ull d; asm("mul.rn.f32x2 %0, %1, %2;" : "=l"(d) : "l"(a), "l"(b)); return d;
}
__device__ __forceinline__ ull fma2(ull a, ull b, ull c) {
    ull d; asm("fma.rn.f32x2 %0, %1, %2, %3;" : "=l"(d) : "l"(a), "l"(b), "l"(c)); return d;
}
__device__ __forceinline__ ull add2(ull a, ull b) {
    ull d; asm("add.rn.f32x2 %0, %1, %2;" : "=l"(d) : "l"(a), "l"(b)); return d;
}
__device__ __forceinline__ ull dup2(float v) {
    ull r; asm("mov.b64 %0, {%1, %1};" : "=l"(r) : "f"(v)); return r;
}

// ---------------- interior: h in [4, 124), no row clamping, reg-dieted ----------------
__global__ __launch_bounds__(256, 3)
void dwconv_interior(const float* __restrict__ x,
                     const float* __restrict__ ksa,
                     float* __restrict__ out)
{
    const int tx = threadIdx.x;                 // 0..63 -> w-pair
    const int ty = threadIdx.y;                 // 0..3
    const int h  = (blockIdx.x + 1) * TH + ty;  // 4..123
    const int n  = blockIdx.y;
    const int c0 = blockIdx.z * CPB;
    const int w0 = tx * 2;

    // ksa -> packed regs; only COLUMN masking needed (rows all in-bounds)
    ull kk2[25];
    {
        const float* ksabase = ksa + ((size_t)(n * 25) * HH + h) * WW + w0;
        #pragma unroll
        for (int t = 0; t < 25; t++) {
            float2 v = *(const float2*)(ksabase + (size_t)t * HH * WW);
            const int j = t % 5;
            const int cA = w0 + j - 2;
            const int cB = cA + 1;
            v.x = (cA >= 0 && cA < WW) ? v.x : 0.0f;
            v.y = (cB >= 0 && cB < WW) ? v.y : 0.0f;
            kk2[t] = pack2(v.x, v.y);
        }
    }

    const int e0 = (w0 - 2 < 0) ? 0 : (w0 - 2);
    const int e2 = (w0 + 2 > WW - 2) ? (WW - 2) : (w0 + 2);

    // three column-base pointers at tap-row 0 (= image row h-2); row i = +i*WW (imm)
    const size_t chbase = (size_t)(n * CHN + c0) * HH * WW + (size_t)(h - 2) * WW;
    const float* pA = x + chbase + e0;
    const float* pB = x + chbase + w0;
    const float* pC = x + chbase + e2;
    float* outp = out + ((size_t)(n * CHN + c0) * HH + h) * WW + w0;

    #pragma unroll 1
    for (int cl = 0; cl < CPB; ++cl) {
        const float* wc = c_w + (c0 + cl) * 25;
        ull accA = dup2(c_b[c0 + cl]);
        ull accB = 0ULL;

        #pragma unroll
        for (int i = 0; i < 5; i++) {
            const float2 A = *(const float2*)(pA + i * WW);   // imm displacement
            const float2 B = *(const float2*)(pB + i * WW);
            const float2 C = *(const float2*)(pC + i * WW);
            accA = fma2(mul2(kk2[i*5+0], dup2(wc[i*5+0])), pack2(A.x, A.y), accA);
            accB = fma2(mul2(kk2[i*5+1], dup2(wc[i*5+1])), pack2(A.y, B.x), accB);
            accA = fma2(mul2(kk2[i*5+2], dup2(wc[i*5+2])), pack2(B.x, B.y), accA);
            accB = fma2(mul2(kk2[i*5+3], dup2(wc[i*5+3])), pack2(B.y, C.x), accB);
            accA = fma2(mul2(kk2[i*5+4], dup2(wc[i*5+4])), pack2(C.x, C.y), accA);
        }

        float a0, a1;
        unpack2(add2(accA, accB), a0, a1);
        *(float2*)outp = make_float2(a0, a1);

        pA += HH * WW; pB += HH * WW; pC += HH * WW; outp += HH * WW;
    }
}

// ---------------- edge: h in {0..3, 124..127}, full clamping ----------------
__global__ __launch_bounds__(256, 2)
void dwconv_edge(const float* __restrict__ x,
                 const float* __restrict__ ksa,
                 float* __restrict__ out)
{
    const int tx = threadIdx.x;
    const int ty = threadIdx.y;
    const int h  = (blockIdx.x == 0 ? 0 : HH - TH) + ty;
    const int n  = blockIdx.y;
    const int c0 = blockIdx.z * CPB;
    const int w0 = tx * 2;

    ull kk2[25];
    const float* ksabase = ksa + ((size_t)(n * 25) * HH + h) * WW + w0;
    #pragma unroll
    for (int t = 0; t < 25; t++) {
        float2 v = *(const float2*)(ksabase + (size_t)t * HH * WW);
        const int i = t / 5, j = t % 5;
        const int r = h + i - 2;
        const bool rok = (r >= 0) && (r < HH);
        const int cA = w0 + j - 2;
        const int cB = cA + 1;
        v.x = (rok && cA >= 0 && cA < WW) ? v.x : 0.0f;
        v.y = (rok && cB >= 0 && cB < WW) ? v.y : 0.0f;
        kk2[t] = pack2(v.x, v.y);
    }

    int rowoff[5];
    #pragma unroll
    for (int i = 0; i < 5; i++) {
        int r = h + i - 2;
        r = r < 0 ? 0 : (r > HH - 1 ? HH - 1 : r);
        rowoff[i] = r * WW;
    }
    const int e0 = (w0 - 2 < 0) ? 0 : (w0 - 2);
    const int e2 = (w0 + 2 > WW - 2) ? (WW - 2) : (w0 + 2);

    const float* xn   = x   + (size_t)(n * CHN + c0) * HH * WW;
    float*       outp = out + ((size_t)(n * CHN + c0) * HH + h) * WW + w0;

    #pragma unroll 1
    for (int cl = 0; cl < CPB; ++cl) {
        const float* xc = xn + (size_t)cl * HH * WW;
        const float* wc = c_w + (c0 + cl) * 25;
        ull accA = dup2(c_b[c0 + cl]);
        ull accB = 0ULL;

        #pragma unroll
        for (int i = 0; i < 5; i++) {
            const float* row = xc + rowoff[i];
            const float2 A = *(const float2*)(row + e0);
            const float2 B = *(const float2*)(row + w0);
            const float2 C = *(const float2*)(row + e2);
            accA = fma2(mul2(kk2[i*5+0], dup2(wc[i*5+0])), pack2(A.x, A.y), accA);
            accB = fma2(mul2(kk2[i*5+1], dup2(wc[i*5+1])), pack2(A.y, B.x), accB);
            accA = fma2(mul2(kk2[i*5+2], dup2(wc[i*5+2])), pack2(B.x, B.y), accA);
            accB = fma2(mul2(kk2[i*5+3], dup2(wc[i*5+3])), pack2(B.y, C.x), accB);
            accA = fma2(mul2(kk2[i*5+4], dup2(wc[i*5+4])), pack2(C.x, C.y), accA);
        }

        float a0, a1;
        unpack2(add2(accA, accB), a0, a1);
        *(float2*)(outp + (size_t)cl * HH * WW) = make_float2(a0, a1);
    }
}

extern "C" void kernel_launch(void* const* d_in, const int* in_sizes, int n_in,
                              void* d_out, int out_size)
{
    const float* x   = (const float*)d_in[0];
    const float* ksa = (const float*)d_in[1];
    const float* w   = (const float*)d_in[2];
    const float* b   = (const float*)d_in[3];
    float* out = (float*)d_out;

    const int n_batch = in_sizes[0] / (CHN * HH * WW);   // 4

    cudaMemcpyToSymbolAsync(c_w, w, CHN * 25 * sizeof(float), 0, cudaMemcpyDeviceToDevice);
    cudaMemcpyToSymbolAsync(c_b, b, CHN * sizeof(float), 0, cudaMemcpyDeviceToDevice);

    dim3 block(64, TH);
    dim3 gridI(HH / TH - 2, n_batch, CSPLIT);   // h in [4,124)
    dim3 gridE(2,           n_batch, CSPLIT);   // h in {0..3, 124..127}
    dwconv_interior<<<gridI, block>>>(x, ksa, out);
    dwconv_edge<<<gridE, block>>>(x, ksa, out);
}